// round 1
// baseline (speedup 1.0000x reference)
#include <cuda_runtime.h>
#include <cstdint>

#define E_CNT 3200000
#define N_CNT 100000

// Packed pe layout: stride 112 floats/edge.
//   layer1: cols [0,50)   (pad 50..51 = 0)
//   layer2: cols [52,77)  (pad 77..79 = 0)
//   layer3: cols [80,112)
// All offsets are multiples of 4 -> float4-aligned everywhere.

// ---------------- scratch (device globals; no allocation allowed) -----------
__device__ float g_pe[(size_t)E_CNT * 112];   // 1.43 GB
__device__ float g_WeP[64 * 112];
__device__ float g_bP[112];
__device__ float g_ph[N_CNT * 52];            // padded per-layer stride (52/28/32)
__device__ float g_acc[N_CNT * 52];
__device__ float g_h1[N_CNT * 52];            // layer1 output, stride 52 (50 real)
__device__ float g_h2[N_CNT * 28];            // layer2 output, stride 28 (25 real)

// ---------------- weight packing -------------------------------------------
__global__ void pack_weights(const float* __restrict__ Wm1, const float* __restrict__ bm1,
                             const float* __restrict__ Wm2, const float* __restrict__ bm2,
                             const float* __restrict__ Wm3, const float* __restrict__ bm3) {
    int idx = blockIdx.x * blockDim.x + threadIdx.x;
    if (idx < 112) {
        float b = 0.f;
        if (idx < 50)                 b = bm1[idx];
        else if (idx >= 52 && idx < 77) b = bm2[idx - 52];
        else if (idx >= 80)           b = bm3[idx - 80];
        g_bP[idx] = b;
    }
    for (int i = idx; i < 64 * 112; i += blockDim.x * gridDim.x) {
        int k = i / 112, j = i % 112;
        float w = 0.f;
        // e-part rows: Wm1 rows [64,128), Wm2 rows [50,114), Wm3 rows [25,89)
        if (j < 50)                 w = Wm1[(64 + k) * 50 + j];
        else if (j >= 52 && j < 77) w = Wm2[(50 + k) * 25 + (j - 52)];
        else if (j >= 80)           w = Wm3[(25 + k) * 32 + (j - 80)];
        g_WeP[i] = w;
    }
}

// ---------------- edge GEMM: pe[E,112] = efeats[E,64] @ WeP + bP ------------
// 512 threads/block, 128 edges/block. Thread = (tx in 16 j-groups of 7) x
// (ty in 32 edge-groups of 4). 4x7 register tile per thread.
__global__ void __launch_bounds__(512) edge_gemm(const float* __restrict__ ef) {
    extern __shared__ float sm[];
    float* sW = sm;                 // 7168
    float* sB = sm + 7168;          // 112
    float* sE = sm + 7280;          // 128 * 68 (padded rows)

    int t = threadIdx.x;
    for (int i = t; i < 64 * 112; i += 512) sW[i] = g_WeP[i];
    if (t < 112) sB[t] = g_bP[t];

    int ebase = blockIdx.x * 128;
    // load 128 edge rows (64 floats each) as float4, padded stride 68
    for (int i = t; i < 128 * 16; i += 512) {
        int r = i >> 4, q = i & 15;
        float4 v = *(const float4*)&ef[(size_t)(ebase + r) * 64 + q * 4];
        *(float4*)&sE[r * 68 + q * 4] = v;
    }
    __syncthreads();

    int tx = t & 15, ty = t >> 4;
    int jb = tx * 7;
    int eb = ty * 4;

    float acc[4][7];
#pragma unroll
    for (int i = 0; i < 4; i++)
#pragma unroll
        for (int u = 0; u < 7; u++) acc[i][u] = sB[jb + u];

#pragma unroll 4
    for (int k = 0; k < 64; k++) {
        float e0 = sE[(eb + 0) * 68 + k];
        float e1 = sE[(eb + 1) * 68 + k];
        float e2 = sE[(eb + 2) * 68 + k];
        float e3 = sE[(eb + 3) * 68 + k];
        float w[7];
#pragma unroll
        for (int u = 0; u < 7; u++) w[u] = sW[k * 112 + jb + u];
#pragma unroll
        for (int u = 0; u < 7; u++) {
            acc[0][u] += e0 * w[u];
            acc[1][u] += e1 * w[u];
            acc[2][u] += e2 * w[u];
            acc[3][u] += e3 * w[u];
        }
    }

#pragma unroll
    for (int i = 0; i < 4; i++) {
        size_t base = (size_t)(ebase + eb + i) * 112 + jb;
#pragma unroll
        for (int u = 0; u < 7; u++) g_pe[base + u] = acc[i][u];
    }
}

// ---------------- node pre-GEMM: ph = h @ Wm_h; zero acc --------------------
// Wm_h = first K rows of Wm (fan_out = F). blockDim (64,4).
template<int K, int F, int FP, int HS>
__global__ void node_pre(const float* __restrict__ h, const float* __restrict__ Wm) {
    __shared__ float sW[K * F];
    int tid = threadIdx.y * 64 + threadIdx.x;
    for (int i = tid; i < K * F; i += 256) sW[i] = Wm[i];
    __syncthreads();

    int node = blockIdx.x * 4 + threadIdx.y;
    int tx = threadIdx.x;
    float a = 0.f;
    if (tx < F) {
        const float* hr = h + (size_t)node * HS;
#pragma unroll 4
        for (int k = 0; k < K; k++) a += hr[k] * sW[k * F + tx];
    }
    if (tx < FP) {
        g_ph[node * FP + tx]  = a;   // pads write 0
        g_acc[node * FP + tx] = 0.f;
    }
}

// ---------------- edge scatter: acc[dst] += relu(ph[src] + pe[e]) -----------
template<int FP, int OFF>
__global__ void scatter_kernel(const int* __restrict__ src, const int* __restrict__ dst) {
    constexpr int NV = FP / 4;
    int idx = blockIdx.x * blockDim.x + threadIdx.x;
    if (idx >= E_CNT * NV) return;
    int e = idx / NV;
    int c = idx - e * NV;
    int s = src[e];
    int d = dst[e];
    const float4 pv = *(const float4*)&g_pe[(size_t)e * 112 + OFF + 4 * c];
    const float4 hv = *(const float4*)&g_ph[(size_t)s * FP + 4 * c];
    float x = fmaxf(pv.x + hv.x, 0.f);
    float y = fmaxf(pv.y + hv.y, 0.f);
    float z = fmaxf(pv.z + hv.z, 0.f);
    float w = fmaxf(pv.w + hv.w, 0.f);
    float* a = &g_acc[(size_t)d * FP + 4 * c];
    asm volatile("red.global.add.v4.f32 [%0], {%1, %2, %3, %4};"
                 :: "l"(a), "f"(x), "f"(y), "f"(z), "f"(w) : "memory");
}

// ---------------- node apply: h' = relu(cat(h, acc) @ Wa + ba) --------------
template<int FH, int HS, int FN, int FNP, int FOUT, int FOUTP, int OSTR>
__global__ void node_apply(const float* __restrict__ h, const float* __restrict__ Wa,
                           const float* __restrict__ ba, float* __restrict__ out) {
    __shared__ float sW[(FH + FN) * FOUT];
    int tid = threadIdx.y * 64 + threadIdx.x;
    for (int i = tid; i < (FH + FN) * FOUT; i += 256) sW[i] = Wa[i];
    __syncthreads();

    int node = blockIdx.x * 4 + threadIdx.y;
    int tx = threadIdx.x;
    float a = 0.f;
    if (tx < FOUT) {
        a = ba[tx];
        const float* hr = h + (size_t)node * HS;
#pragma unroll 4
        for (int k = 0; k < FH; k++) a += hr[k] * sW[k * FOUT + tx];
        const float* nr = g_acc + (size_t)node * FNP;
#pragma unroll 4
        for (int k = 0; k < FN; k++) a += nr[k] * sW[(FH + k) * FOUT + tx];
        a = fmaxf(a, 0.f);
    }
    if (tx < FOUTP) out[(size_t)node * OSTR + tx] = a;  // pads -> 0
}

// ---------------- launch ----------------------------------------------------
extern "C" void kernel_launch(void* const* d_in, const int* in_sizes, int n_in,
                              void* d_out, int out_size) {
    const float* nfeats = (const float*)d_in[0];
    const float* efeats = (const float*)d_in[1];
    const int*   src    = (const int*)d_in[2];
    const int*   dst    = (const int*)d_in[3];
    const float* Wm1 = (const float*)d_in[4];  const float* bm1 = (const float*)d_in[5];
    const float* Wa1 = (const float*)d_in[6];  const float* ba1 = (const float*)d_in[7];
    const float* Wm2 = (const float*)d_in[8];  const float* bm2 = (const float*)d_in[9];
    const float* Wa2 = (const float*)d_in[10]; const float* ba2 = (const float*)d_in[11];
    const float* Wm3 = (const float*)d_in[12]; const float* bm3 = (const float*)d_in[13];
    const float* Wa3 = (const float*)d_in[14]; const float* ba3 = (const float*)d_in[15];
    float* out = (float*)d_out;

    void *h1p_, *h2p_;
    cudaGetSymbolAddress(&h1p_, g_h1);
    cudaGetSymbolAddress(&h2p_, g_h2);
    float* h1p = (float*)h1p_;
    float* h2p = (float*)h2p_;

    pack_weights<<<28, 256>>>(Wm1, bm1, Wm2, bm2, Wm3, bm3);

    size_t smem = (size_t)(7168 + 112 + 128 * 68) * 4;   // ~62.4 KB
    cudaFuncSetAttribute(edge_gemm, cudaFuncAttributeMaxDynamicSharedMemorySize, (int)smem);
    edge_gemm<<<E_CNT / 128, 512, smem>>>(efeats);

    dim3 nb(64, 4);
    int ngrid = N_CNT / 4;

    // ---- layer 1 ----
    node_pre<64, 50, 52, 64><<<ngrid, nb>>>(nfeats, Wm1);
    scatter_kernel<52, 0><<<(E_CNT * 13 + 255) / 256, 256>>>(src, dst);
    node_apply<64, 64, 50, 52, 50, 52, 52><<<ngrid, nb>>>(nfeats, Wa1, ba1, h1p);

    // ---- layer 2 ----
    node_pre<50, 25, 28, 52><<<ngrid, nb>>>(h1p, Wm2);
    scatter_kernel<28, 52><<<(E_CNT * 7 + 255) / 256, 256>>>(src, dst);
    node_apply<50, 52, 25, 28, 25, 28, 28><<<ngrid, nb>>>(h1p, Wa2, ba2, h2p);

    // ---- layer 3 ----
    node_pre<25, 32, 32, 28><<<ngrid, nb>>>(h2p, Wm3);
    scatter_kernel<32, 80><<<(E_CNT * 8 + 255) / 256, 256>>>(src, dst);
    node_apply<25, 28, 32, 32, 32, 32, 32><<<ngrid, nb>>>(h2p, Wa3, ba3, out);
}

// round 3
// speedup vs baseline: 1.9539x; 1.9539x over previous
#include <cuda_runtime.h>
#include <cstdint>

#define E_CNT 3200000
#define N_CNT 100000

// Packed pe layout: stride 112 floats/edge.
//   layer1: cols [0,50)  layer2: cols [52,77)  layer3: cols [80,112)

// ---------------- scratch ----------------------------------------------------
__device__ float g_pe[(size_t)E_CNT * 112];   // 1.43 GB
__device__ float g_WN[112 * 64];              // W^T, tf32-rounded: WN[n][k]
__device__ float g_bP[112];
__device__ float g_ph[N_CNT * 52];
__device__ float g_acc[N_CNT * 52];
__device__ float g_h1[N_CNT * 52];
__device__ float g_h2[N_CNT * 28];

__device__ __forceinline__ uint32_t f2tf32(float f) {
    uint32_t u;
    asm("cvt.rna.tf32.f32 %0, %1;" : "=r"(u) : "f"(f));
    return u;
}

// ---------------- weight packing ---------------------------------------------
__global__ void pack_weights(const float* __restrict__ Wm1, const float* __restrict__ bm1,
                             const float* __restrict__ Wm2, const float* __restrict__ bm2,
                             const float* __restrict__ Wm3, const float* __restrict__ bm3) {
    int idx = blockIdx.x * blockDim.x + threadIdx.x;
    if (idx < 112) {
        float b = 0.f;
        if (idx < 50)                   b = bm1[idx];
        else if (idx >= 52 && idx < 77) b = bm2[idx - 52];
        else if (idx >= 80)             b = bm3[idx - 80];
        g_bP[idx] = b;
    }
    for (int i = idx; i < 112 * 64; i += blockDim.x * gridDim.x) {
        int n = i / 64, k = i % 64;
        float w = 0.f;
        if (n < 50)                   w = Wm1[(64 + k) * 50 + n];
        else if (n >= 52 && n < 77)   w = Wm2[(50 + k) * 25 + (n - 52)];
        else if (n >= 80)             w = Wm3[(25 + k) * 32 + (n - 80)];
        g_WN[i] = __uint_as_float(f2tf32(w));
    }
}

// ---------------- tf32 mma.sync edge GEMM ------------------------------------
// pe[E,112] = tf32(efeats[E,64]) @ tf32(W) + bias.
// Block: 256 thr = 8 warps = (warp_m 0..3) x (warp_n 0..1).
// Warp tile: 32 rows x 56 cols; mma m16n8k8: 2 m-tiles x 7 n-tiles x 8 k-steps.
// SMEM: sA 128x68 u32 (tf32 bits), sB [k=64][n=120] u32, bias 112 f.
#define SA_STRIDE 68
#define SB_STRIDE 120
#define SM_A_OFF  0
#define SM_B_OFF  (128 * SA_STRIDE * 4)                 // 34816
#define SM_BIAS_OFF (SM_B_OFF + 64 * SB_STRIDE * 4)     // 65536
#define SM_TOTAL  (SM_BIAS_OFF + 112 * 4)               // 65984

__device__ __forceinline__ void mma_tf32(float c[4], uint32_t a0, uint32_t a1,
                                         uint32_t a2, uint32_t a3,
                                         uint32_t b0, uint32_t b1) {
    asm volatile(
        "mma.sync.aligned.m16n8k8.row.col.f32.tf32.tf32.f32 "
        "{%0,%1,%2,%3}, {%4,%5,%6,%7}, {%8,%9}, {%0,%1,%2,%3};"
        : "+f"(c[0]), "+f"(c[1]), "+f"(c[2]), "+f"(c[3])
        : "r"(a0), "r"(a1), "r"(a2), "r"(a3), "r"(b0), "r"(b1));
}

__global__ void __launch_bounds__(256, 2) edge_gemm_mma(const float* __restrict__ ef) {
    extern __shared__ char smraw[];
    uint32_t* sA = (uint32_t*)(smraw + SM_A_OFF);
    uint32_t* sB = (uint32_t*)(smraw + SM_B_OFF);
    float* sBias = (float*)(smraw + SM_BIAS_OFF);

    int t = threadIdx.x;
    int wid = t >> 5, lane = t & 31;
    int warp_m = wid & 3, warp_n = wid >> 2;
    int lq = lane >> 2;        // 0..7
    int lr = lane & 3;         // 0..3

    // one-time: B tile [k][n] + bias
    for (int i = t; i < 112 * 64; i += 256) {
        int n = i / 64, k = i % 64;
        sB[k * SB_STRIDE + n] = __float_as_uint(g_WN[i]);
    }
    if (t < 112) sBias[t] = g_bP[t];
    __syncthreads();

    const int a_row0 = warp_m * 32 + lq;
    const int b_col0 = warp_n * 56 + lq;

    for (int tile = blockIdx.x; tile < E_CNT / 128; tile += gridDim.x) {
        // ---- A tile: 128 edges x 64 fp32 (contiguous 32KB) -> tf32 smem ----
        const float4* asrc = (const float4*)(ef + (size_t)tile * 128 * 64);
#pragma unroll
        for (int j = 0; j < 8; j++) {
            int i = j * 256 + t;
            int r = i >> 4, k4 = i & 15;
            float4 v = asrc[i];
            uint4 u;
            u.x = f2tf32(v.x); u.y = f2tf32(v.y);
            u.z = f2tf32(v.z); u.w = f2tf32(v.w);
            *(uint4*)&sA[r * SA_STRIDE + k4 * 4] = u;
        }
        __syncthreads();

        // ---- compute ----
        float c[2][7][4];
#pragma unroll
        for (int mt = 0; mt < 2; mt++)
#pragma unroll
            for (int nt = 0; nt < 7; nt++)
#pragma unroll
                for (int q = 0; q < 4; q++) c[mt][nt][q] = 0.f;

#pragma unroll
        for (int s = 0; s < 8; s++) {
            int kc = s * 8 + lr;
            uint32_t a[2][4];
#pragma unroll
            for (int mt = 0; mt < 2; mt++) {
                int r = a_row0 + mt * 16;
                a[mt][0] = sA[r * SA_STRIDE + kc];
                a[mt][1] = sA[(r + 8) * SA_STRIDE + kc];
                a[mt][2] = sA[r * SA_STRIDE + kc + 4];
                a[mt][3] = sA[(r + 8) * SA_STRIDE + kc + 4];
            }
#pragma unroll
            for (int nt = 0; nt < 7; nt++) {
                uint32_t b0 = sB[kc * SB_STRIDE + b_col0 + nt * 8];
                uint32_t b1 = sB[(kc + 4) * SB_STRIDE + b_col0 + nt * 8];
                mma_tf32(c[0][nt], a[0][0], a[0][1], a[0][2], a[0][3], b0, b1);
                mma_tf32(c[1][nt], a[1][0], a[1][1], a[1][2], a[1][3], b0, b1);
            }
        }

        // ---- epilogue: bias add + direct STG.v2 ----
        float* dstp = g_pe + (size_t)tile * 128 * 112;
#pragma unroll
        for (int nt = 0; nt < 7; nt++) {
            int col = warp_n * 56 + nt * 8 + lr * 2;
            float bx = sBias[col], by = sBias[col + 1];
#pragma unroll
            for (int mt = 0; mt < 2; mt++) {
                int row = warp_m * 32 + mt * 16 + lq;
                float2 v0 = make_float2(c[mt][nt][0] + bx, c[mt][nt][1] + by);
                float2 v1 = make_float2(c[mt][nt][2] + bx, c[mt][nt][3] + by);
                *(float2*)&dstp[(size_t)row * 112 + col] = v0;
                *(float2*)&dstp[(size_t)(row + 8) * 112 + col] = v1;
            }
        }
        __syncthreads();   // sA reused next iteration
    }
}

// ---------------- node pre-GEMM ----------------------------------------------
template<int K, int F, int FP, int HS>
__global__ void node_pre(const float* __restrict__ h, const float* __restrict__ Wm) {
    __shared__ float sW[K * F];
    int tid = threadIdx.y * 64 + threadIdx.x;
    for (int i = tid; i < K * F; i += 256) sW[i] = Wm[i];
    __syncthreads();
    int node = blockIdx.x * 4 + threadIdx.y;
    int tx = threadIdx.x;
    float a = 0.f;
    if (tx < F) {
        const float* hr = h + (size_t)node * HS;
#pragma unroll 4
        for (int k = 0; k < K; k++) a += hr[k] * sW[k * F + tx];
    }
    if (tx < FP) {
        g_ph[node * FP + tx]  = a;
        g_acc[node * FP + tx] = 0.f;
    }
}

// ---------------- edge scatter ------------------------------------------------
template<int FP, int OFF>
__global__ void scatter_kernel(const int* __restrict__ src, const int* __restrict__ dst) {
    constexpr int NV = FP / 4;
    int idx = blockIdx.x * blockDim.x + threadIdx.x;
    if (idx >= E_CNT * NV) return;
    int e = idx / NV;
    int c = idx - e * NV;
    int s = src[e];
    int d = dst[e];
    const float4 pv = *(const float4*)&g_pe[(size_t)e * 112 + OFF + 4 * c];
    const float4 hv = *(const float4*)&g_ph[(size_t)s * FP + 4 * c];
    float x = fmaxf(pv.x + hv.x, 0.f);
    float y = fmaxf(pv.y + hv.y, 0.f);
    float z = fmaxf(pv.z + hv.z, 0.f);
    float w = fmaxf(pv.w + hv.w, 0.f);
    float* a = &g_acc[(size_t)d * FP + 4 * c];
    asm volatile("red.global.add.v4.f32 [%0], {%1, %2, %3, %4};"
                 :: "l"(a), "f"(x), "f"(y), "f"(z), "f"(w) : "memory");
}

// ---------------- node apply --------------------------------------------------
template<int FH, int HS, int FN, int FNP, int FOUT, int FOUTP, int OSTR>
__global__ void node_apply(const float* __restrict__ h, const float* __restrict__ Wa,
                           const float* __restrict__ ba, float* __restrict__ out) {
    __shared__ float sW[(FH + FN) * FOUT];
    int tid = threadIdx.y * 64 + threadIdx.x;
    for (int i = tid; i < (FH + FN) * FOUT; i += 256) sW[i] = Wa[i];
    __syncthreads();
    int node = blockIdx.x * 4 + threadIdx.y;
    int tx = threadIdx.x;
    float a = 0.f;
    if (tx < FOUT) {
        a = ba[tx];
        const float* hr = h + (size_t)node * HS;
#pragma unroll 4
        for (int k = 0; k < FH; k++) a += hr[k] * sW[k * FOUT + tx];
        const float* nr = g_acc + (size_t)node * FNP;
#pragma unroll 4
        for (int k = 0; k < FN; k++) a += nr[k] * sW[(FH + k) * FOUT + tx];
        a = fmaxf(a, 0.f);
    }
    if (tx < FOUTP) out[(size_t)node * OSTR + tx] = a;
}

// ---------------- launch ------------------------------------------------------
extern "C" void kernel_launch(void* const* d_in, const int* in_sizes, int n_in,
                              void* d_out, int out_size) {
    const float* nfeats = (const float*)d_in[0];
    const float* efeats = (const float*)d_in[1];
    const int*   src    = (const int*)d_in[2];
    const int*   dst    = (const int*)d_in[3];
    const float* Wm1 = (const float*)d_in[4];  const float* bm1 = (const float*)d_in[5];
    const float* Wa1 = (const float*)d_in[6];  const float* ba1 = (const float*)d_in[7];
    const float* Wm2 = (const float*)d_in[8];  const float* bm2 = (const float*)d_in[9];
    const float* Wa2 = (const float*)d_in[10]; const float* ba2 = (const float*)d_in[11];
    const float* Wm3 = (const float*)d_in[12]; const float* bm3 = (const float*)d_in[13];
    const float* Wa3 = (const float*)d_in[14]; const float* ba3 = (const float*)d_in[15];
    float* out = (float*)d_out;

    void *h1p_, *h2p_;
    cudaGetSymbolAddress(&h1p_, g_h1);
    cudaGetSymbolAddress(&h2p_, g_h2);
    float* h1p = (float*)h1p_;
    float* h2p = (float*)h2p_;

    pack_weights<<<28, 256>>>(Wm1, bm1, Wm2, bm2, Wm3, bm3);

    cudaFuncSetAttribute(edge_gemm_mma, cudaFuncAttributeMaxDynamicSharedMemorySize, SM_TOTAL);
    edge_gemm_mma<<<296, 256, SM_TOTAL>>>(efeats);

    dim3 nb(64, 4);
    int ngrid = N_CNT / 4;

    node_pre<64, 50, 52, 64><<<ngrid, nb>>>(nfeats, Wm1);
    scatter_kernel<52, 0><<<(E_CNT * 13 + 255) / 256, 256>>>(src, dst);
    node_apply<64, 64, 50, 52, 50, 52, 52><<<ngrid, nb>>>(nfeats, Wa1, ba1, h1p);

    node_pre<50, 25, 28, 52><<<ngrid, nb>>>(h1p, Wm2);
    scatter_kernel<28, 52><<<(E_CNT * 7 + 255) / 256, 256>>>(src, dst);
    node_apply<50, 52, 25, 28, 25, 28, 28><<<ngrid, nb>>>(h1p, Wa2, ba2, h2p);

    node_pre<25, 32, 32, 28><<<ngrid, nb>>>(h2p, Wm3);
    scatter_kernel<32, 80><<<(E_CNT * 8 + 255) / 256, 256>>>(src, dst);
    node_apply<25, 28, 32, 32, 32, 32, 32><<<ngrid, nb>>>(h2p, Wa3, ba3, out);
}